// round 1
// baseline (speedup 1.0000x reference)
#include <cuda_runtime.h>
#include <cuda_fp16.h>
#include <mma.h>

using namespace nvcuda;

#define B_  256
#define T_  256
#define D_  128
#define H_  1024
#define O_  128
#define FH  4096

// ---------------- scratch (static __device__ globals; no allocations) ----------------
__device__ __half g_Wcat0[(size_t)FH * 1152];   // [W_ih0 | W_hh0] rows, K=1152
__device__ __half g_Wcat1[(size_t)FH * 2048];   // [W_ih1 | W_hh1] rows, K=2048
__device__ float  g_bias0[FH];                  // b_ih0 + b_hh0
__device__ float  g_bias1[FH];
__device__ __half g_X16[(size_t)B_ * T_ * D_];  // x in fp16, [B,T,D]
__device__ __half g_ha[2][B_ * H_];             // layer0 hidden, double buffered
__device__ __half g_hb[2][B_ * H_];             // layer1 hidden, double buffered
__device__ float  g_ca[B_ * H_];                // layer0 cell (in-place)
__device__ float  g_cb[B_ * H_];                // layer1 cell (in-place)
__device__ float  g_hb32[B_ * H_];              // final-step layer1 hidden, fp32

// ---------------- helpers ----------------
__device__ __forceinline__ void cp16(void* dst, const void* src) {
    unsigned d = (unsigned)__cvta_generic_to_shared(dst);
    asm volatile("cp.async.cg.shared.global [%0], [%1], 16;" :: "r"(d), "l"(src));
}
__device__ __forceinline__ void cp_commit() { asm volatile("cp.async.commit_group;"); }
template <int N> __device__ __forceinline__ void cp_wait() {
    asm volatile("cp.async.wait_group %0;" :: "n"(N));
}
__device__ __forceinline__ float sigm(float v) { return 1.f / (1.f + expf(-v)); }

// ---------------- prep: pack weights fp32->fp16, biases, init state ----------------
__global__ void prep_kernel(
    const float* __restrict__ x,    const float* __restrict__ h0,   const float* __restrict__ c0,
    const float* __restrict__ Wih0, const float* __restrict__ Whh0,
    const float* __restrict__ bih0, const float* __restrict__ bhh0,
    const float* __restrict__ Wih1, const float* __restrict__ Whh1,
    const float* __restrict__ bih1, const float* __restrict__ bhh1)
{
    size_t tid    = (size_t)blockIdx.x * blockDim.x + threadIdx.x;
    size_t stride = (size_t)gridDim.x * blockDim.x;

    for (size_t i = tid; i < (size_t)FH * 2048; i += stride) {
        size_t n = i >> 11; int kk = (int)(i & 2047);
        float v = (kk < 1024) ? Wih1[n * 1024 + kk] : Whh1[n * 1024 + (kk - 1024)];
        g_Wcat1[i] = __float2half(v);
    }
    for (size_t i = tid; i < (size_t)FH * 1152; i += stride) {
        size_t n = i / 1152; int kk = (int)(i - n * 1152);
        float v = (kk < 128) ? Wih0[n * 128 + kk] : Whh0[n * 1024 + (kk - 128)];
        g_Wcat0[i] = __float2half(v);
    }
    for (size_t i = tid; i < (size_t)B_ * T_ * D_; i += stride)
        g_X16[i] = __float2half(x[i]);
    for (size_t i = tid; i < (size_t)B_ * H_; i += stride) {
        __half h = __float2half(h0[i]);
        g_ha[0][i] = h;          // ha_{-1}
        g_hb[1][i] = h;          // hb_{-1} (read at step 1 from buffer [1])
        g_ca[i] = c0[i];
        g_cb[i] = c0[i];
    }
    for (size_t i = tid; i < FH; i += stride) {
        g_bias0[i] = bih0[i] + bhh0[i];
        g_bias1[i] = bih1[i] + bhh1[i];
    }
}

// ---------------- fused step: GEMM (wmma fp16) + LSTM cell ----------------
// launch `step` in [0, T_]:
//   task 0 (CTAs 0..63):   layer0 cell at time `step`      (skipped when step == T_)
//   task 1 (CTAs 64..127): layer1 cell at time `step - 1`  (skipped when step == 0)
// CTA tile: BM=128 (batch), N = 4 gates x 32 h-columns. 2 M-tiles x 32 N-tiles per task.
__global__ void __launch_bounds__(256) step_kernel(int step)
{
    extern __shared__ char smem[];
    __half* As = (__half*)smem;            // [2][128][24]
    __half* Bs = As + 2 * 128 * 24;        // [2][128][24]   (total 24 KB)
    float*  gs = (float*)smem;             // epilogue reuse: [64][128] fp32 (32 KB)

    const int task  = blockIdx.x >> 6;
    const int tile  = blockIdx.x & 63;
    const int mtile = tile >> 5;           // 0..1
    const int ntile = tile & 31;           // 0..31
    if (task == 0 && step >= T_) return;
    if (task == 1 && step == 0)  return;

    const int tid   = threadIdx.x;
    const int hbase = ntile * 32;

    const __half* haS  = g_ha[step & 1];
    const __half* hbS  = g_hb[step & 1];
    const __half* W    = task ? g_Wcat1 : g_Wcat0;
    const float*  bias = task ? g_bias1 : g_bias0;
    const int     ldw  = task ? 2048 : 1152;
    const int     nK   = task ? 128  : 72;       // K/16

    // per-thread load geometry: 256 threads cover 128 rows x 16 cols as 16B vectors
    const int am = tid >> 1;
    const int ac = (tid & 1) * 8;
    const int ab = mtile * 128 + am;
    const int br = tid >> 1;
    const int bc = (tid & 1) * 8;
    const int bg = br >> 5, bj = br & 31;
    const __half* Wrow = W + (size_t)(bg * 1024 + hbase + bj) * ldw;

    auto load_tile = [&](int ks, int stg) {
        int kg = ks * 16 + ac;
        const __half* src;
        if (task == 0)
            src = (kg < 128) ? (g_X16 + ((size_t)ab * T_ + step) * D_ + kg)
                             : (haS + (size_t)ab * H_ + (kg - 128));
        else
            src = (kg < 1024) ? (haS + (size_t)ab * H_ + kg)
                              : (hbS + (size_t)ab * H_ + (kg - 1024));
        cp16(As + stg * (128 * 24) + am * 24 + ac, src);
        cp16(Bs + stg * (128 * 24) + br * 24 + bc, Wrow + ks * 16 + bc);
        cp_commit();
    };

    const int warp = tid >> 5;
    const int wm   = warp >> 1;   // 0..3 -> rows [wm*32, +32)
    const int wn2  = warp & 1;    // 0..1 -> cols [wn2*64, +64)

    wmma::fragment<wmma::accumulator, 16, 16, 16, float> acc[2][4];
    #pragma unroll
    for (int i = 0; i < 2; i++)
        #pragma unroll
        for (int t2 = 0; t2 < 4; t2++)
            wmma::fill_fragment(acc[i][t2], 0.f);

    load_tile(0, 0);
    for (int ks = 0; ks < nK; ++ks) {
        int cur = ks & 1;
        if (ks + 1 < nK) { load_tile(ks + 1, cur ^ 1); cp_wait<1>(); }
        else             { cp_wait<0>(); }
        __syncthreads();

        wmma::fragment<wmma::matrix_a, 16, 16, 16, __half, wmma::row_major> af[2];
        wmma::fragment<wmma::matrix_b, 16, 16, 16, __half, wmma::col_major> bf[4];
        const __half* Ab = As + cur * (128 * 24);
        const __half* Bb = Bs + cur * (128 * 24);
        #pragma unroll
        for (int i = 0; i < 2; i++)
            wmma::load_matrix_sync(af[i], Ab + (wm * 32 + i * 16) * 24, 24);
        #pragma unroll
        for (int t2 = 0; t2 < 4; t2++)
            wmma::load_matrix_sync(bf[t2], Bb + (wn2 * 64 + t2 * 16) * 24, 24);
        #pragma unroll
        for (int i = 0; i < 2; i++)
            #pragma unroll
            for (int t2 = 0; t2 < 4; t2++)
                wmma::mma_sync(acc[i][t2], af[i], bf[t2], acc[i][t2]);
        __syncthreads();
    }

    // -------- epilogue: 2 phases of 64 rows through SMEM, fused LSTM cell --------
    float*  cbuf = task ? g_cb : g_ca;
    __half* hdst = task ? g_hb[(step + 1) & 1] : g_ha[(step + 1) & 1];
    const bool wr32 = (task == 1) && (step == T_);

    for (int phase = 0; phase < 2; ++phase) {
        __syncthreads();
        if ((wm >> 1) == phase) {
            #pragma unroll
            for (int i = 0; i < 2; i++)
                #pragma unroll
                for (int t2 = 0; t2 < 4; t2++)
                    wmma::store_matrix_sync(
                        gs + (size_t)((wm & 1) * 32 + i * 16) * 128 + wn2 * 64 + t2 * 16,
                        acc[i][t2], 128, wmma::mem_row_major);
        }
        __syncthreads();
        for (int idx = tid; idx < 64 * 32; idx += 256) {
            int r = idx >> 5, j = idx & 31;
            int m = phase * 64 + r;
            int b = mtile * 128 + m;
            int h = hbase + j;
            float ig = gs[r * 128 +       j] + bias[           h];
            float fg = gs[r * 128 + 32 +  j] + bias[1024 +     h];
            float gg = gs[r * 128 + 64 +  j] + bias[2048 +     h];
            float og = gs[r * 128 + 96 +  j] + bias[3072 +     h];
            size_t off = (size_t)b * H_ + h;
            float cn = sigm(fg) * cbuf[off] + sigm(ig) * tanhf(gg);
            cbuf[off] = cn;
            float hn = sigm(og) * tanhf(cn);
            hdst[off] = __float2half(hn);
            if (wr32) g_hb32[off] = hn;
        }
    }
}

// ---------------- output projection: out = hb_255 @ W_out^T + b_out (fp32) ----------------
__global__ void __launch_bounds__(256) out_kernel(
    const float* __restrict__ Wout, const float* __restrict__ bout, float* __restrict__ out)
{
    __shared__ float hrow[H_];
    int b = blockIdx.x;
    for (int i = threadIdx.x; i < H_; i += 256) hrow[i] = g_hb32[(size_t)b * H_ + i];
    __syncthreads();
    int warp = threadIdx.x >> 5, lane = threadIdx.x & 31;
    for (int o = warp * 16; o < warp * 16 + 16; ++o) {
        float s = 0.f;
        for (int h = lane; h < H_; h += 32) s += hrow[h] * Wout[(size_t)o * H_ + h];
        #pragma unroll
        for (int off = 16; off; off >>= 1) s += __shfl_down_sync(0xffffffffu, s, off);
        if (lane == 0) out[(size_t)b * O_ + o] = s + bout[o];
    }
}

// ---------------- launch ----------------
extern "C" void kernel_launch(void* const* d_in, const int* in_sizes, int n_in,
                              void* d_out, int out_size)
{
    const float* x    = (const float*)d_in[0];
    const float* h0   = (const float*)d_in[1];
    const float* c0   = (const float*)d_in[2];
    const float* Wih0 = (const float*)d_in[3];
    const float* Whh0 = (const float*)d_in[4];
    const float* bih0 = (const float*)d_in[5];
    const float* bhh0 = (const float*)d_in[6];
    const float* Wih1 = (const float*)d_in[7];
    const float* Whh1 = (const float*)d_in[8];
    const float* bih1 = (const float*)d_in[9];
    const float* bhh1 = (const float*)d_in[10];
    const float* Wout = (const float*)d_in[11];
    const float* bout = (const float*)d_in[12];
    float* out = (float*)d_out;

    prep_kernel<<<2048, 256>>>(x, h0, c0, Wih0, Whh0, bih0, bhh0, Wih1, Whh1, bih1, bhh1);

    const int smem_bytes = 64 * 128 * 4;  // 32 KB (>= 24 KB GEMM stages)
    for (int s = 0; s <= T_; ++s)
        step_kernel<<<128, 256, smem_bytes>>>(s);

    out_kernel<<<B_, 256>>>(Wout, bout, out);
}

// round 7
// speedup vs baseline: 1.6591x; 1.6591x over previous
#include <cuda_runtime.h>
#include <cuda_fp16.h>
#include <mma.h>
#include <cstdint>

using namespace nvcuda;

#define B_  256
#define T_  256
#define D_  128
#define H_  1024
#define O_  128
#define FH  4096

// ---------------- persistent scratch ----------------
__device__ __half g_Wcat0[(size_t)FH * 1152];   // [W_ih0 | W_hh0], K=1152, row-major
__device__ __half g_Wcat1[(size_t)FH * 2048];   // [W_ih1 | W_hh1], K=2048
__device__ float  g_bias0[FH];
__device__ float  g_bias1[FH];
__device__ __half g_X16[(size_t)B_ * T_ * D_];  // [B][T][D]
__device__ __half g_ha[2][B_ * H_];
__device__ __half g_hb[2][B_ * H_];
__device__ float  g_ca[B_ * H_];
__device__ float  g_cb[B_ * H_];
__device__ float  g_hb32[B_ * H_];

// ---------------- helpers ----------------
__device__ __forceinline__ void cp16(void* dst, const void* src) {
    unsigned d = (unsigned)__cvta_generic_to_shared(dst);
    asm volatile("cp.async.cg.shared.global [%0], [%1], 16;" :: "r"(d), "l"(src));
}
__device__ __forceinline__ void cp_commit() { asm volatile("cp.async.commit_group;"); }
template <int N> __device__ __forceinline__ void cp_wait() {
    asm volatile("cp.async.wait_group %0;" :: "n"(N));
}
__device__ __forceinline__ float sigm(float v) { return 1.f / (1.f + __expf(-v)); }

// ---------------- prep ----------------
__global__ void prep_kernel(
    const float* __restrict__ x,    const float* __restrict__ h0,   const float* __restrict__ c0,
    const float* __restrict__ Wih0, const float* __restrict__ Whh0,
    const float* __restrict__ bih0, const float* __restrict__ bhh0,
    const float* __restrict__ Wih1, const float* __restrict__ Whh1,
    const float* __restrict__ bih1, const float* __restrict__ bhh1)
{
    size_t tid    = (size_t)blockIdx.x * blockDim.x + threadIdx.x;
    size_t stride = (size_t)gridDim.x * blockDim.x;

    for (size_t i = tid; i < (size_t)FH * 2048; i += stride) {
        size_t n = i >> 11; int kk = (int)(i & 2047);
        float v = (kk < 1024) ? Wih1[n * 1024 + kk] : Whh1[n * 1024 + (kk - 1024)];
        g_Wcat1[i] = __float2half(v);
    }
    for (size_t i = tid; i < (size_t)FH * 1152; i += stride) {
        size_t n = i / 1152; int kk = (int)(i - n * 1152);
        float v = (kk < 128) ? Wih0[n * 128 + kk] : Whh0[n * 1024 + (kk - 128)];
        g_Wcat0[i] = __float2half(v);
    }
    for (size_t i = tid; i < (size_t)B_ * T_ * D_; i += stride)
        g_X16[i] = __float2half(x[i]);
    for (size_t i = tid; i < (size_t)B_ * H_; i += stride) {
        __half h = __float2half(h0[i]);
        g_ha[0][i] = h;          // ha_{-1}
        g_hb[1][i] = h;          // hb_{-1}
        g_ca[i] = c0[i];
        g_cb[i] = c0[i];
    }
    for (size_t i = tid; i < FH; i += stride) {
        g_bias0[i] = bih0[i] + bhh0[i];
        g_bias1[i] = bih1[i] + bhh1[i];
    }
}

// ---------------- fused step: wmma GEMM (K-chunk 128) + LSTM cell ----------------
// launch `step` in [0, T_]:
//   CTAs 0..63  : layer0 cell at time `step`      (skip when step == T_)
//   CTAs 64..127: layer1 cell at time `step - 1`  (skip when step == 0)
// CTA tile: M=128 (batch) x N=128 (4 gates x 32 h). 8 warps in 2(M) x 4(N); warp tile 64x32.
// K-chunk = 128, 2-stage cp.async double buffer, padded smem stride 136 halves (272B).
#define KT      128
#define LDS_    136                          // padded stride in halves
#define MAT_H   (128 * LDS_)                 // halves per matrix panel
#define STAGE_H (2 * MAT_H)                  // A + B panel per stage
#define SMEM_SZ (1024 + 2 * STAGE_H * 2 + 256)

__global__ void __launch_bounds__(256) step_kernel(int step)
{
    extern __shared__ char smem[];
    float*  sb  = (float*)smem;              // 128 biases, gate-major col order
    __half* st  = (__half*)(smem + 1024);    // 2 stages of [A|B]
    float*  gs  = (float*)st;                // epilogue reuse of stage 0: [64][128] fp32

    const int task  = blockIdx.x >> 6;
    const int tile  = blockIdx.x & 63;
    const int mtile = tile >> 5;             // 0..1
    const int ntile = tile & 31;             // 0..31
    if (task == 0 && step >= T_) return;
    if (task == 1 && step == 0)  return;

    const int tid   = threadIdx.x;
    const int warp  = tid >> 5;
    const int wm    = warp & 1;              // 0..1 -> rows [wm*64, +64)
    const int wn    = warp >> 1;             // 0..3 -> cols [wn*32, +32)
    const int hbase = ntile * 32;
    const int mbase = mtile * 128;

    const __half* haS  = g_ha[step & 1];
    const __half* hbS  = g_hb[step & 1];
    const __half* W    = task ? g_Wcat1 : g_Wcat0;
    const float*  bias = task ? g_bias1 : g_bias0;
    const int     ldw  = task ? 2048 : 1152;
    const int     nK   = task ? 16 : 9;      // K/128 chunks

    if (tid < 128) sb[tid] = bias[(tid >> 5) * 1024 + hbase + (tid & 31)];

    // ---- chunk loader: A[128 x 128] + B[128 x 128] halves, padded rows ----
    auto load_chunk = [&](int c, int s) {
        __half* As = st + s * STAGE_H;
        __half* Bs = As + MAT_H;
        #pragma unroll
        for (int i = tid; i < 2048; i += 256) {
            int row = i >> 4, v = i & 15;
            int colg = v << 3;
            const __half* asrc;
            if (task == 0)
                asrc = (c == 0) ? (g_X16 + ((size_t)(mbase + row) * T_ + step) * D_ + colg)
                                : (haS + (size_t)(mbase + row) * H_ + (c - 1) * 128 + colg);
            else
                asrc = (c < 8) ? (haS + (size_t)(mbase + row) * H_ + c * 128 + colg)
                               : (hbS + (size_t)(mbase + row) * H_ + (c - 8) * 128 + colg);
            cp16(As + row * LDS_ + colg, asrc);
            int wrow = ((row >> 5) << 10) + hbase + (row & 31);   // gate*1024 + h
            cp16(Bs + row * LDS_ + colg, W + (size_t)wrow * ldw + c * 128 + colg);
        }
        cp_commit();
    };

    wmma::fragment<wmma::accumulator, 16, 16, 16, float> acc[4][2];
    #pragma unroll
    for (int i = 0; i < 4; i++)
        #pragma unroll
        for (int j = 0; j < 2; j++)
            wmma::fill_fragment(acc[i][j], 0.f);

    load_chunk(0, 0);
    for (int k = 0; k < nK; ++k) {
        int cur = k & 1;
        if (k + 1 < nK) { load_chunk(k + 1, cur ^ 1); cp_wait<1>(); }
        else            { cp_wait<0>(); }
        __syncthreads();

        const __half* Ab = st + cur * STAGE_H;
        const __half* Bb = Ab + MAT_H;
        #pragma unroll
        for (int kk = 0; kk < 8; ++kk) {
            wmma::fragment<wmma::matrix_a, 16, 16, 16, __half, wmma::row_major> af[4];
            wmma::fragment<wmma::matrix_b, 16, 16, 16, __half, wmma::col_major> bf[2];
            #pragma unroll
            for (int i = 0; i < 4; i++)
                wmma::load_matrix_sync(af[i], Ab + (wm * 64 + i * 16) * LDS_ + kk * 16, LDS_);
            #pragma unroll
            for (int j = 0; j < 2; j++)
                wmma::load_matrix_sync(bf[j], Bb + (wn * 32 + j * 16) * LDS_ + kk * 16, LDS_);
            #pragma unroll
            for (int i = 0; i < 4; i++)
                #pragma unroll
                for (int j = 0; j < 2; j++)
                    wmma::mma_sync(acc[i][j], af[i], bf[j], acc[i][j]);
        }
        __syncthreads();
    }

    // -------- epilogue: 2 phases of 64 rows through SMEM, fused LSTM cell --------
    float*  cbuf = task ? g_cb : g_ca;
    __half* hdst = task ? g_hb[(step + 1) & 1] : g_ha[(step + 1) & 1];
    const bool wr32 = (task == 1) && (step == T_);

    for (int phase = 0; phase < 2; ++phase) {
        __syncthreads();
        if (wm == phase) {
            #pragma unroll
            for (int i = 0; i < 4; i++)
                #pragma unroll
                for (int j = 0; j < 2; j++)
                    wmma::store_matrix_sync(gs + (size_t)(i * 16) * 128 + wn * 32 + j * 16,
                                            acc[i][j], 128, wmma::mem_row_major);
        }
        __syncthreads();
        for (int idx = tid; idx < 64 * 32; idx += 256) {
            int r = idx >> 5, j = idx & 31;
            int m = phase * 64 + r;
            int b = mbase + m;
            int h = hbase + j;
            float ig = gs[r * 128 +      j] + sb[     j];
            float fg = gs[r * 128 + 32 + j] + sb[32 + j];
            float gg = gs[r * 128 + 64 + j] + sb[64 + j];
            float og = gs[r * 128 + 96 + j] + sb[96 + j];
            size_t off = (size_t)b * H_ + h;
            float cn = sigm(fg) * cbuf[off] + sigm(ig) * tanhf(gg);
            cbuf[off] = cn;
            float hn = sigm(og) * tanhf(cn);
            hdst[off] = __float2half(hn);
            if (wr32) g_hb32[off] = hn;
        }
    }
}

// ---------------- output projection ----------------
__global__ void __launch_bounds__(256) out_kernel(
    const float* __restrict__ Wout, const float* __restrict__ bout, float* __restrict__ out)
{
    __shared__ float hrow[H_];
    int b = blockIdx.x;
    for (int i = threadIdx.x; i < H_; i += 256) hrow[i] = g_hb32[(size_t)b * H_ + i];
    __syncthreads();
    int warp = threadIdx.x >> 5, lane = threadIdx.x & 31;
    for (int o = warp * 16; o < warp * 16 + 16; ++o) {
        float s = 0.f;
        for (int h = lane; h < H_; h += 32) s += hrow[h] * Wout[(size_t)o * H_ + h];
        #pragma unroll
        for (int off = 16; off; off >>= 1) s += __shfl_down_sync(0xffffffffu, s, off);
        if (lane == 0) out[(size_t)b * O_ + o] = s + bout[o];
    }
}

// ---------------- launch ----------------
extern "C" void kernel_launch(void* const* d_in, const int* in_sizes, int n_in,
                              void* d_out, int out_size)
{
    const float* x    = (const float*)d_in[0];
    const float* h0   = (const float*)d_in[1];
    const float* c0   = (const float*)d_in[2];
    const float* Wih0 = (const float*)d_in[3];
    const float* Whh0 = (const float*)d_in[4];
    const float* bih0 = (const float*)d_in[5];
    const float* bhh0 = (const float*)d_in[6];
    const float* Wih1 = (const float*)d_in[7];
    const float* Whh1 = (const float*)d_in[8];
    const float* bih1 = (const float*)d_in[9];
    const float* bhh1 = (const float*)d_in[10];
    const float* Wout = (const float*)d_in[11];
    const float* bout = (const float*)d_in[12];
    float* out = (float*)d_out;

    cudaFuncSetAttribute(step_kernel, cudaFuncAttributeMaxDynamicSharedMemorySize, SMEM_SZ);

    prep_kernel<<<2048, 256>>>(x, h0, c0, Wih0, Whh0, bih0, bhh0, Wih1, Whh1, bih1, bhh1);

    for (int s = 0; s <= T_; ++s)
        step_kernel<<<128, 256, SMEM_SZ>>>(s);

    out_kernel<<<B_, 256>>>(Wout, bout, out);
}